// round 4
// baseline (speedup 1.0000x reference)
#include <cuda_runtime.h>
#include <math.h>

#define NR   65536
#define DIM  256
#define NCW  1024
#define NLEV 4
#define NPAIRS (NCW*(NCW-1)/2)

// -------- device scratch (no allocations allowed) --------
__device__ float g_resid[NR*DIM];            // 64 MB
__device__ float g_rn2[NR];
__device__ float g_wk2[NCW];
__device__ unsigned long long g_key[NR];
__device__ int g_counts[NCW];
__device__ double g_qpart[NR];
__device__ double g_pdpart[NCW];
__device__ double g_scal[3];                 // quant, util, compact accumulators

// -------- init: residual = x, rn2 = sum(x^2) per row, zero scalar accumulators --------
__global__ void init_kernel(const float* __restrict__ x) {
    int n = blockIdx.x, t = threadIdx.x;
    float v = x[n*DIM + t];
    g_resid[n*DIM + t] = v;
    __shared__ float s[DIM];
    s[t] = __fmul_rn(v, v);
    __syncthreads();
    for (int off = 128; off > 0; off >>= 1) {
        if (t < off) s[t] = __fadd_rn(s[t], s[t+off]);
        __syncthreads();
    }
    if (t == 0) g_rn2[n] = s[0];
    if (n == 0 && t < 3) g_scal[t] = 0.0;
}

// -------- per-level prep: reset argmin keys + histogram --------
__global__ void prep_kernel() {
    int i = blockIdx.x * blockDim.x + threadIdx.x;
    g_key[i] = 0xFFFFFFFFFFFFFFFFULL;
    if (i < NCW) g_counts[i] = 0;
}

// -------- codeword squared norms --------
__global__ void wk2_kernel(const float* __restrict__ W) {
    int c = blockIdx.x, t = threadIdx.x;
    float v = W[c*DIM + t];
    __shared__ float s[DIM];
    s[t] = __fmul_rn(v, v);
    __syncthreads();
    for (int off = 128; off > 0; off >>= 1) {
        if (t < off) s[t] = __fadd_rn(s[t], s[t+off]);
        __syncthreads();
    }
    if (t == 0) g_wk2[c] = s[0];
}

// -------- pairwise distance partial sums (compact loss) --------
__global__ void pdist_kernel(const float* __restrict__ W) {
    int i = blockIdx.x, t = threadIdx.x;
    __shared__ float wi[DIM];
    wi[t] = W[i*DIM + t];
    __syncthreads();
    double acc = 0.0;
    float sqi = g_wk2[i];
    for (int j = i + 1 + t; j < NCW; j += 256) {
        const float* wj = W + (size_t)j*DIM;
        float dot = 0.f;
        #pragma unroll 8
        for (int d = 0; d < DIM; d++) dot = __fmaf_rn(wi[d], __ldg(&wj[d]), dot);
        float d2 = __fsub_rn(__fadd_rn(sqi, g_wk2[j]), __fmul_rn(2.f, dot));
        acc += (double)sqrtf(fmaxf(d2, 0.f));
    }
    __shared__ double sd[256];
    sd[t] = acc;
    __syncthreads();
    for (int off = 128; off > 0; off >>= 1) {
        if (t < off) sd[t] += sd[t+off];
        __syncthreads();
    }
    if (t == 0) g_pdpart[i] = sd[0];
}

// -------- main GEMM + argmin kernel: 128x128 tile, BK=32, 8x8 per thread --------
#define BM 128
#define BN 128
#define BK 32

__global__ void __launch_bounds__(256)
gemm_argmin_kernel(const float* __restrict__ W) {
    extern __shared__ float sm[];
    float* As = sm;          // [2][BK][BM]
    float* Bs = sm + 8192;   // [2][BK][BN]

    int t = threadIdx.x;
    int bx = blockIdx.x;     // codeword tile 0..7
    int by = blockIdx.y;     // row tile 0..511
    int rowBase = by * BM;
    int cwBase  = bx * BN;
    int tx = t & 15, ty = t >> 4;

    float acc[8][8];
    #pragma unroll
    for (int i = 0; i < 8; i++)
        #pragma unroll
        for (int j = 0; j < 8; j++) acc[i][j] = 0.f;

    // loader mapping: per thread 4 float4 per tile
    int lrow[4], lk0[4];
    #pragma unroll
    for (int i = 0; i < 4; i++) {
        int f = t + i * 256;          // float4 id 0..1023
        lrow[i] = f >> 3;             // 0..127
        lk0[i]  = (f & 7) * 4;        // 0,4,..,28
    }

    float4 ra[4], rb[4];
    // load chunk 0
    #pragma unroll
    for (int i = 0; i < 4; i++) {
        ra[i] = *(const float4*)&g_resid[(size_t)(rowBase + lrow[i])*DIM + lk0[i]];
        rb[i] = *(const float4*)&W[(size_t)(cwBase + lrow[i])*DIM + lk0[i]];
    }
    #pragma unroll
    for (int i = 0; i < 4; i++) {
        int k0 = lk0[i], r = lrow[i];
        As[(k0+0)*BM + r] = ra[i].x; As[(k0+1)*BM + r] = ra[i].y;
        As[(k0+2)*BM + r] = ra[i].z; As[(k0+3)*BM + r] = ra[i].w;
        Bs[(k0+0)*BN + r] = rb[i].x; Bs[(k0+1)*BN + r] = rb[i].y;
        Bs[(k0+2)*BN + r] = rb[i].z; Bs[(k0+3)*BN + r] = rb[i].w;
    }
    __syncthreads();

    for (int c = 0; c < DIM / BK; c++) {
        int buf = c & 1;
        if (c < DIM/BK - 1) {
            int kc = (c + 1) * BK;
            #pragma unroll
            for (int i = 0; i < 4; i++) {
                ra[i] = *(const float4*)&g_resid[(size_t)(rowBase + lrow[i])*DIM + kc + lk0[i]];
                rb[i] = *(const float4*)&W[(size_t)(cwBase + lrow[i])*DIM + kc + lk0[i]];
            }
        }
        const float* Ab = As + buf * (BK*BM);
        const float* Bb = Bs + buf * (BK*BN);
        #pragma unroll 8
        for (int k = 0; k < BK; k++) {
            float4 a0 = *(const float4*)&Ab[k*BM + ty*8];
            float4 a1 = *(const float4*)&Ab[k*BM + ty*8 + 4];
            float4 b0 = *(const float4*)&Bb[k*BN + tx*8];
            float4 b1 = *(const float4*)&Bb[k*BN + tx*8 + 4];
            float a[8] = {a0.x,a0.y,a0.z,a0.w,a1.x,a1.y,a1.z,a1.w};
            float b[8] = {b0.x,b0.y,b0.z,b0.w,b1.x,b1.y,b1.z,b1.w};
            #pragma unroll
            for (int i = 0; i < 8; i++)
                #pragma unroll
                for (int j = 0; j < 8; j++)
                    acc[i][j] = __fmaf_rn(a[i], b[j], acc[i][j]);
        }
        __syncthreads();
        if (c < DIM/BK - 1) {
            int nb = buf ^ 1;
            #pragma unroll
            for (int i = 0; i < 4; i++) {
                int k0 = lk0[i], r = lrow[i];
                float* Aw = As + nb * (BK*BM);
                float* Bw = Bs + nb * (BK*BN);
                Aw[(k0+0)*BM + r] = ra[i].x; Aw[(k0+1)*BM + r] = ra[i].y;
                Aw[(k0+2)*BM + r] = ra[i].z; Aw[(k0+3)*BM + r] = ra[i].w;
                Bw[(k0+0)*BN + r] = rb[i].x; Bw[(k0+1)*BN + r] = rb[i].y;
                Bw[(k0+2)*BN + r] = rb[i].z; Bw[(k0+3)*BN + r] = rb[i].w;
            }
            __syncthreads();
        }
    }

    // epilogue: dist = fl(fl(rn2 + wk2) - fl(2*dot)), argmin with first-index tie-break
    int rows0 = rowBase + ty * 8;
    int cols0 = cwBase + tx * 8;
    float wk[8];
    #pragma unroll
    for (int j = 0; j < 8; j++) wk[j] = __ldg(&g_wk2[cols0 + j]);

    #pragma unroll
    for (int i = 0; i < 8; i++) {
        float rn = __ldg(&g_rn2[rows0 + i]);
        unsigned long long best = 0xFFFFFFFFFFFFFFFFULL;
        #pragma unroll
        for (int j = 0; j < 8; j++) {
            float dist = __fsub_rn(__fadd_rn(rn, wk[j]), __fmul_rn(2.f, acc[i][j]));
            unsigned u = __float_as_uint(dist);
            u = (u & 0x80000000u) ? ~u : (u | 0x80000000u);
            unsigned long long key = ((unsigned long long)u << 32) | (unsigned)(cols0 + j);
            best = min(best, key);
        }
        #pragma unroll
        for (int off = 8; off > 0; off >>= 1) {
            unsigned long long o = __shfl_xor_sync(0xFFFFFFFFu, best, off);
            best = min(best, o);
        }
        if (tx == 0) atomicMin(&g_key[rows0 + i], best);
    }
}

// -------- per-row update: gather, straight-through, residual, losses --------
__global__ void update_kernel(const float* __restrict__ x, const float* __restrict__ W,
                              float* __restrict__ quant, float* __restrict__ out_idx,
                              int first) {
    int n = blockIdx.x, t = threadIdx.x;
    unsigned idx = (unsigned)(g_key[n] & 0xFFFFFFFFULL);
    size_t e = (size_t)n * DIM + t;
    float r = g_resid[e];
    float q = W[(size_t)idx * DIM + t];
    float diff = __fsub_rn(q, r);              // q - residual (both losses use this value)
    float qst  = __fadd_rn(r, diff);           // straight-through value
    float qz   = first ? qst : __fadd_rn(quant[e], qst);
    quant[e] = qz;
    float rnew = __fsub_rn(x[e], qz);
    g_resid[e] = rnew;

    __shared__ float  sf[DIM];
    __shared__ double sd[DIM];
    sf[t] = __fmul_rn(rnew, rnew);
    sd[t] = (double)diff * (double)diff;
    __syncthreads();
    for (int off = 128; off > 0; off >>= 1) {
        if (t < off) { sf[t] = __fadd_rn(sf[t], sf[t+off]); sd[t] += sd[t+off]; }
        __syncthreads();
    }
    if (t == 0) {
        g_rn2[n]  = sf[0];
        g_qpart[n] = sd[0];
        out_idx[n] = (float)idx;
        atomicAdd(&g_counts[idx], 1);
    }
}

// -------- per-level scalar reductions (deterministic), includes pdist fold --------
__global__ void level_reduce_kernel() {
    __shared__ double sd[1024];
    int t = threadIdx.x;
    double a = 0.0;
    for (int i = t; i < NR; i += 1024) a += g_qpart[i];
    sd[t] = a;
    __syncthreads();
    for (int off = 512; off > 0; off >>= 1) {
        if (t < off) sd[t] += sd[t+off];
        __syncthreads();
    }
    if (t == 0) {
        double m = sd[0] / ((double)NR * (double)DIM);
        g_scal[0] += m + 0.25 * m;     // q_latent + COMMIT_W * e_latent
    }
    __syncthreads();
    sd[t] = fabs((double)g_counts[t] - 64.0);
    __syncthreads();
    for (int off = 512; off > 0; off >>= 1) {
        if (t < off) sd[t] += sd[t+off];
        __syncthreads();
    }
    if (t == 0) g_scal[1] += sd[0] / (double)NCW;
    __syncthreads();
    sd[t] = g_pdpart[t];
    __syncthreads();
    for (int off = 512; off > 0; off >>= 1) {
        if (t < off) sd[t] += sd[t+off];
        __syncthreads();
    }
    if (t == 0) g_scal[2] += 2.0 * (sd[0] / (double)NPAIRS);
}

__global__ void finalize_kernel(float* __restrict__ scal_out) {
    if (threadIdx.x < 3) scal_out[threadIdx.x] = (float)g_scal[threadIdx.x];
}

// -------- host driver --------
extern "C" void kernel_launch(void* const* d_in, const int* in_sizes, int n_in,
                              void* d_out, int out_size) {
    const float* x  = (const float*)d_in[0];
    const float* cb = (const float*)d_in[1];
    float* out   = (float*)d_out;
    float* quant = out;                       // [65536*256]
    float* scal  = out + (size_t)NR * DIM;    // [3]
    float* oidx  = scal + 3;                  // [4*65536]

    cudaFuncSetAttribute(gemm_argmin_kernel,
                         cudaFuncAttributeMaxDynamicSharedMemorySize, 65536);

    init_kernel<<<NR, 256>>>(x);
    for (int c = 0; c < NLEV; c++) {
        const float* W = cb + (size_t)c * NCW * DIM;
        prep_kernel<<<NR/256, 256>>>();
        wk2_kernel<<<NCW, 256>>>(W);
        pdist_kernel<<<NCW, 256>>>(W);
        dim3 grid(NCW/BN, NR/BM);
        gemm_argmin_kernel<<<grid, 256, 65536>>>(W);
        update_kernel<<<NR, 256>>>(x, W, quant, oidx + (size_t)c * NR, c == 0 ? 1 : 0);
        level_reduce_kernel<<<1, 1024>>>();
    }
    finalize_kernel<<<1, 32>>>(scal);
}

// round 5
// speedup vs baseline: 1.4001x; 1.4001x over previous
#include <cuda_runtime.h>
#include <math.h>

#define NR   65536
#define DIM  256
#define NCW  1024
#define NLEV 4
#define NPAIRS (NCW*(NCW-1)/2)
#define PD_BLOCKS 36   // 8x8 upper-triangular tile pairs

// -------- device scratch (no allocations allowed) --------
__device__ float g_resid[NR*DIM];            // 64 MB
__device__ float g_rn2[NR];
__device__ float g_wk2[NCW];
__device__ unsigned long long g_key[NR];
__device__ int g_counts[NCW];
__device__ double g_qpart[NR];
__device__ double g_pdpart[PD_BLOCKS];
__device__ double g_scal[3];                 // quant, util, compact accumulators

// -------- packed fp32x2 helpers (sm_103a FFMA2) --------
__device__ __forceinline__ unsigned long long pack2(float x, float y) {
    unsigned long long r;
    asm("mov.b64 %0,{%1,%2};" : "=l"(r) : "f"(x), "f"(y));
    return r;
}
__device__ __forceinline__ void fma2(unsigned long long& d,
                                     unsigned long long a, unsigned long long b) {
    asm("fma.rn.f32x2 %0,%1,%2,%0;" : "+l"(d) : "l"(a), "l"(b));
}
__device__ __forceinline__ void unpack2(unsigned long long v, float& x, float& y) {
    asm("mov.b64 {%0,%1},%2;" : "=f"(x), "=f"(y) : "l"(v));
}

// -------- init: residual = x, rn2 = sum(x^2) per row, zero scalar accumulators --------
__global__ void init_kernel(const float* __restrict__ x) {
    int n = blockIdx.x, t = threadIdx.x;
    float v = x[n*DIM + t];
    g_resid[n*DIM + t] = v;
    __shared__ float s[DIM];
    s[t] = __fmul_rn(v, v);
    __syncthreads();
    for (int off = 128; off > 0; off >>= 1) {
        if (t < off) s[t] = __fadd_rn(s[t], s[t+off]);
        __syncthreads();
    }
    if (t == 0) g_rn2[n] = s[0];
    if (n == 0 && t < 3) g_scal[t] = 0.0;
}

// -------- per-level prep: reset argmin keys + histogram --------
__global__ void prep_kernel() {
    int i = blockIdx.x * blockDim.x + threadIdx.x;
    g_key[i] = 0xFFFFFFFFFFFFFFFFULL;
    if (i < NCW) g_counts[i] = 0;
}

// -------- codeword squared norms --------
__global__ void wk2_kernel(const float* __restrict__ W) {
    int c = blockIdx.x, t = threadIdx.x;
    float v = W[c*DIM + t];
    __shared__ float s[DIM];
    s[t] = __fmul_rn(v, v);
    __syncthreads();
    for (int off = 128; off > 0; off >>= 1) {
        if (t < off) s[t] = __fadd_rn(s[t], s[t+off]);
        __syncthreads();
    }
    if (t == 0) g_wk2[c] = s[0];
}

// -------- pairwise distances (compact loss): tiled Gram kernel --------
// 36 blocks covering 8x8 upper-triangular 128x128 tile pairs.
#define PDK 32
__global__ void __launch_bounds__(256)
pdist_kernel(const float* __restrict__ W) {
    // decode block -> (ti, tj), ti <= tj
    int b = blockIdx.x, ti = 0;
    while (b >= 8 - ti) { b -= 8 - ti; ti++; }
    int tj = ti + b;

    __shared__ float sA[PDK][128];
    __shared__ float sB[PDK][128];

    int t = threadIdx.x;
    int tx = t & 15, ty = t >> 4;
    int rowBase = ti * 128, colBase = tj * 128;

    float acc[8][8];
    #pragma unroll
    for (int i = 0; i < 8; i++)
        #pragma unroll
        for (int j = 0; j < 8; j++) acc[i][j] = 0.f;

    // loader: 256 threads x 4 float4 = 128 rows x 32 cols per tile
    int lrow = t >> 1;                 // 0..127
    int lc0  = (t & 1) * 16;           // 0 or 16

    for (int kc = 0; kc < DIM; kc += PDK) {
        #pragma unroll
        for (int q = 0; q < 4; q++) {
            float4 va = *(const float4*)&W[(size_t)(rowBase + lrow)*DIM + kc + lc0 + q*4];
            float4 vb = *(const float4*)&W[(size_t)(colBase + lrow)*DIM + kc + lc0 + q*4];
            sA[lc0 + q*4 + 0][lrow] = va.x; sA[lc0 + q*4 + 1][lrow] = va.y;
            sA[lc0 + q*4 + 2][lrow] = va.z; sA[lc0 + q*4 + 3][lrow] = va.w;
            sB[lc0 + q*4 + 0][lrow] = vb.x; sB[lc0 + q*4 + 1][lrow] = vb.y;
            sB[lc0 + q*4 + 2][lrow] = vb.z; sB[lc0 + q*4 + 3][lrow] = vb.w;
        }
        __syncthreads();
        #pragma unroll 8
        for (int k = 0; k < PDK; k++) {
            float4 a0 = *(const float4*)&sA[k][ty*8];
            float4 a1 = *(const float4*)&sA[k][ty*8 + 4];
            float4 b0 = *(const float4*)&sB[k][tx*8];
            float4 b1 = *(const float4*)&sB[k][tx*8 + 4];
            float a[8] = {a0.x,a0.y,a0.z,a0.w,a1.x,a1.y,a1.z,a1.w};
            float bb[8] = {b0.x,b0.y,b0.z,b0.w,b1.x,b1.y,b1.z,b1.w};
            #pragma unroll
            for (int i = 0; i < 8; i++)
                #pragma unroll
                for (int j = 0; j < 8; j++)
                    acc[i][j] = __fmaf_rn(a[i], bb[j], acc[i][j]);
        }
        __syncthreads();
    }

    double dsum = 0.0;
    #pragma unroll
    for (int i = 0; i < 8; i++) {
        int gi = rowBase + ty*8 + i;
        float sqi = g_wk2[gi];
        #pragma unroll
        for (int j = 0; j < 8; j++) {
            int gj = colBase + tx*8 + j;
            if (gj > gi) {
                float d2 = __fsub_rn(__fadd_rn(sqi, g_wk2[gj]),
                                     __fmul_rn(2.f, acc[i][j]));
                dsum += (double)sqrtf(fmaxf(d2, 0.f));
            }
        }
    }
    __shared__ double sd[256];
    sd[t] = dsum;
    __syncthreads();
    for (int off = 128; off > 0; off >>= 1) {
        if (t < off) sd[t] += sd[t+off];
        __syncthreads();
    }
    if (t == 0) g_pdpart[blockIdx.x] = sd[0];
}

// -------- main GEMM + argmin kernel: 128x128 tile, BK=32, 8x8 per thread, FFMA2 --------
#define BM 128
#define BN 128
#define BK 32

__global__ void __launch_bounds__(256)
gemm_argmin_kernel(const float* __restrict__ W) {
    extern __shared__ float sm[];
    float* As = sm;          // [2][BK][BM]
    float* Bs = sm + 8192;   // [2][BK][BN]

    int t = threadIdx.x;
    int bx = blockIdx.x;     // codeword tile 0..7
    int by = blockIdx.y;     // row tile 0..511
    int rowBase = by * BM;
    int cwBase  = bx * BN;
    int tx = t & 15, ty = t >> 4;

    // packed accumulators: acc2[i][j2] holds (acc[i][2*j2], acc[i][2*j2+1])
    unsigned long long acc2[8][4];
    #pragma unroll
    for (int i = 0; i < 8; i++)
        #pragma unroll
        for (int j = 0; j < 4; j++) acc2[i][j] = 0ULL;

    // loader mapping: per thread 4 float4 per tile
    int lrow[4], lk0[4];
    #pragma unroll
    for (int i = 0; i < 4; i++) {
        int f = t + i * 256;          // float4 id 0..1023
        lrow[i] = f >> 3;             // 0..127
        lk0[i]  = (f & 7) * 4;        // 0,4,..,28
    }

    float4 ra[4], rb[4];
    #pragma unroll
    for (int i = 0; i < 4; i++) {
        ra[i] = *(const float4*)&g_resid[(size_t)(rowBase + lrow[i])*DIM + lk0[i]];
        rb[i] = *(const float4*)&W[(size_t)(cwBase + lrow[i])*DIM + lk0[i]];
    }
    #pragma unroll
    for (int i = 0; i < 4; i++) {
        int k0 = lk0[i], r = lrow[i];
        As[(k0+0)*BM + r] = ra[i].x; As[(k0+1)*BM + r] = ra[i].y;
        As[(k0+2)*BM + r] = ra[i].z; As[(k0+3)*BM + r] = ra[i].w;
        Bs[(k0+0)*BN + r] = rb[i].x; Bs[(k0+1)*BN + r] = rb[i].y;
        Bs[(k0+2)*BN + r] = rb[i].z; Bs[(k0+3)*BN + r] = rb[i].w;
    }
    __syncthreads();

    for (int c = 0; c < DIM / BK; c++) {
        int buf = c & 1;
        if (c < DIM/BK - 1) {
            int kc = (c + 1) * BK;
            #pragma unroll
            for (int i = 0; i < 4; i++) {
                ra[i] = *(const float4*)&g_resid[(size_t)(rowBase + lrow[i])*DIM + kc + lk0[i]];
                rb[i] = *(const float4*)&W[(size_t)(cwBase + lrow[i])*DIM + kc + lk0[i]];
            }
        }
        const float* Ab = As + buf * (BK*BM);
        const float* Bb = Bs + buf * (BK*BN);
        #pragma unroll 8
        for (int k = 0; k < BK; k++) {
            float4 a0 = *(const float4*)&Ab[k*BM + ty*8];
            float4 a1 = *(const float4*)&Ab[k*BM + ty*8 + 4];
            // b pairs loaded directly as packed 64-bit values (no repack MOVs)
            ulonglong2 bu0 = *(const ulonglong2*)&Bb[k*BN + tx*8];
            ulonglong2 bu1 = *(const ulonglong2*)&Bb[k*BN + tx*8 + 4];
            float a[8] = {a0.x,a0.y,a0.z,a0.w,a1.x,a1.y,a1.z,a1.w};
            #pragma unroll
            for (int i = 0; i < 8; i++) {
                unsigned long long ap = pack2(a[i], a[i]);
                fma2(acc2[i][0], ap, bu0.x);
                fma2(acc2[i][1], ap, bu0.y);
                fma2(acc2[i][2], ap, bu1.x);
                fma2(acc2[i][3], ap, bu1.y);
            }
        }
        __syncthreads();
        if (c < DIM/BK - 1) {
            int nb = buf ^ 1;
            #pragma unroll
            for (int i = 0; i < 4; i++) {
                int k0 = lk0[i], r = lrow[i];
                float* Aw = As + nb * (BK*BM);
                float* Bw = Bs + nb * (BK*BN);
                Aw[(k0+0)*BM + r] = ra[i].x; Aw[(k0+1)*BM + r] = ra[i].y;
                Aw[(k0+2)*BM + r] = ra[i].z; Aw[(k0+3)*BM + r] = ra[i].w;
                Bw[(k0+0)*BN + r] = rb[i].x; Bw[(k0+1)*BN + r] = rb[i].y;
                Bw[(k0+2)*BN + r] = rb[i].z; Bw[(k0+3)*BN + r] = rb[i].w;
            }
            __syncthreads();
        }
    }

    // epilogue: dist = fl(fl(rn2 + wk2) - fl(2*dot)), argmin with first-index tie-break
    int rows0 = rowBase + ty * 8;
    int cols0 = cwBase + tx * 8;
    float wk[8];
    #pragma unroll
    for (int j = 0; j < 8; j++) wk[j] = __ldg(&g_wk2[cols0 + j]);

    #pragma unroll
    for (int i = 0; i < 8; i++) {
        float accf[8];
        #pragma unroll
        for (int j2 = 0; j2 < 4; j2++) unpack2(acc2[i][j2], accf[2*j2], accf[2*j2+1]);
        float rn = __ldg(&g_rn2[rows0 + i]);
        unsigned long long best = 0xFFFFFFFFFFFFFFFFULL;
        #pragma unroll
        for (int j = 0; j < 8; j++) {
            float dist = __fsub_rn(__fadd_rn(rn, wk[j]), __fmul_rn(2.f, accf[j]));
            unsigned u = __float_as_uint(dist);
            u = (u & 0x80000000u) ? ~u : (u | 0x80000000u);
            unsigned long long key = ((unsigned long long)u << 32) | (unsigned)(cols0 + j);
            best = min(best, key);
        }
        #pragma unroll
        for (int off = 8; off > 0; off >>= 1) {
            unsigned long long o = __shfl_xor_sync(0xFFFFFFFFu, best, off);
            best = min(best, o);
        }
        if (tx == 0) atomicMin(&g_key[rows0 + i], best);
    }
}

// -------- per-row update: gather, straight-through, residual, losses --------
__global__ void update_kernel(const float* __restrict__ x, const float* __restrict__ W,
                              float* __restrict__ quant, float* __restrict__ out_idx,
                              int first) {
    int n = blockIdx.x, t = threadIdx.x;
    unsigned idx = (unsigned)(g_key[n] & 0xFFFFFFFFULL);
    size_t e = (size_t)n * DIM + t;
    float r = g_resid[e];
    float q = W[(size_t)idx * DIM + t];
    float diff = __fsub_rn(q, r);              // q - residual (both losses use this value)
    float qst  = __fadd_rn(r, diff);           // straight-through value
    float qz   = first ? qst : __fadd_rn(quant[e], qst);
    quant[e] = qz;
    float rnew = __fsub_rn(x[e], qz);
    g_resid[e] = rnew;

    __shared__ float  sf[DIM];
    __shared__ double sd[DIM];
    sf[t] = __fmul_rn(rnew, rnew);
    sd[t] = (double)diff * (double)diff;
    __syncthreads();
    for (int off = 128; off > 0; off >>= 1) {
        if (t < off) { sf[t] = __fadd_rn(sf[t], sf[t+off]); sd[t] += sd[t+off]; }
        __syncthreads();
    }
    if (t == 0) {
        g_rn2[n]  = sf[0];
        g_qpart[n] = sd[0];
        out_idx[n] = (float)idx;
        atomicAdd(&g_counts[idx], 1);
    }
}

// -------- per-level scalar reductions (deterministic), includes pdist fold --------
__global__ void level_reduce_kernel() {
    __shared__ double sd[1024];
    int t = threadIdx.x;
    double a = 0.0;
    for (int i = t; i < NR; i += 1024) a += g_qpart[i];
    sd[t] = a;
    __syncthreads();
    for (int off = 512; off > 0; off >>= 1) {
        if (t < off) sd[t] += sd[t+off];
        __syncthreads();
    }
    if (t == 0) {
        double m = sd[0] / ((double)NR * (double)DIM);
        g_scal[0] += m + 0.25 * m;     // q_latent + COMMIT_W * e_latent
    }
    __syncthreads();
    sd[t] = fabs((double)g_counts[t] - 64.0);
    __syncthreads();
    for (int off = 512; off > 0; off >>= 1) {
        if (t < off) sd[t] += sd[t+off];
        __syncthreads();
    }
    if (t == 0) g_scal[1] += sd[0] / (double)NCW;
    __syncthreads();
    sd[t] = (t < PD_BLOCKS) ? g_pdpart[t] : 0.0;
    __syncthreads();
    for (int off = 512; off > 0; off >>= 1) {
        if (t < off) sd[t] += sd[t+off];
        __syncthreads();
    }
    if (t == 0) g_scal[2] += 2.0 * (sd[0] / (double)NPAIRS);
}

__global__ void finalize_kernel(float* __restrict__ scal_out) {
    if (threadIdx.x < 3) scal_out[threadIdx.x] = (float)g_scal[threadIdx.x];
}

// -------- host driver --------
extern "C" void kernel_launch(void* const* d_in, const int* in_sizes, int n_in,
                              void* d_out, int out_size) {
    const float* x  = (const float*)d_in[0];
    const float* cb = (const float*)d_in[1];
    float* out   = (float*)d_out;
    float* quant = out;                       // [65536*256]
    float* scal  = out + (size_t)NR * DIM;    // [3]
    float* oidx  = scal + 3;                  // [4*65536]

    cudaFuncSetAttribute(gemm_argmin_kernel,
                         cudaFuncAttributeMaxDynamicSharedMemorySize, 65536);

    init_kernel<<<NR, 256>>>(x);
    for (int c = 0; c < NLEV; c++) {
        const float* W = cb + (size_t)c * NCW * DIM;
        prep_kernel<<<NR/256, 256>>>();
        wk2_kernel<<<NCW, 256>>>(W);
        pdist_kernel<<<PD_BLOCKS, 256>>>(W);
        dim3 grid(NCW/BN, NR/BM);
        gemm_argmin_kernel<<<grid, 256, 65536>>>(W);
        update_kernel<<<NR, 256>>>(x, W, quant, oidx + (size_t)c * NR, c == 0 ? 1 : 0);
        level_reduce_kernel<<<1, 1024>>>();
    }
    finalize_kernel<<<1, 32>>>(scal);
}